// round 7
// baseline (speedup 1.0000x reference)
#include <cuda_runtime.h>
#include <cuda_fp16.h>

#define C_CH   256
#define Hf     100
#define Wf     100
#define HWf    (Hf * Wf)
#define GRIDP  8
#define OUTP   7
#define HALF_C 128

// NHWC scratch in fp16: [B][H][W][C], B<=2. 16B-aligned for vector access.
__device__ __align__(16) __half g_featT[2 * HWf * C_CH];

// ---------------------------------------------------------------------------
// Kernel 1: NCHW fp32 -> NHWC fp16 transpose.
// Tile 64 channels x 32 hw. Block (32,8) = 256 threads.
// Load: lanes over hw (128B/warp). Store: half2 with lanes over channels
// (32 lanes x 4B = 128B contiguous per warp request).
// ---------------------------------------------------------------------------
__global__ void nchw_to_nhwc_kernel(const float* __restrict__ in) {
    __shared__ float tile[64][33];
    const int b   = blockIdx.z;
    const int hw0 = blockIdx.x * 32;
    const int c0  = blockIdx.y * 64;
    const int tx  = threadIdx.x;            // 0..31
    const int ty  = threadIdx.y;            // 0..7

    const float* inb = in + (size_t)b * C_CH * HWf;
    const int hw_l = hw0 + tx;
    if (hw_l < HWf) {
        #pragma unroll
        for (int j = 0; j < 8; ++j) {
            int cl = ty + j * 8;             // 0..63
            tile[cl][tx] = inb[(size_t)(c0 + cl) * HWf + hw_l];
        }
    }
    __syncthreads();

    __half* outb = g_featT + (size_t)b * HWf * C_CH;
    #pragma unroll
    for (int j = 0; j < 4; ++j) {
        int hwl = ty + j * 8;                // 0..31
        int hw  = hw0 + hwl;
        if (hw < HWf) {
            __half2 h = __floats2half2_rn(tile[2 * tx][hwl], tile[2 * tx + 1][hwl]);
            *(__half2*)(outb + (size_t)hw * C_CH + c0 + 2 * tx) = h;
        }
    }
}

// ---------------------------------------------------------------------------
// Kernel 2: RoIAlign (8x8 grid) + 2x2/s1 avg pool.
// block = (roi n, channel-half of 128), 128 threads, thread = ONE channel
// (scalar). Same 25KB smem now hosts 4 warps/block -> ~2x warps in flight
// vs the 64-thread float2 version. fp16 scalar taps: 64B/warp-request = 1
// L1 wavefront, same tap bytes. Tap loads batched in two half-row groups
// of 16 to bound register live ranges (reg cap 64 via launch_bounds).
// ---------------------------------------------------------------------------
__global__ __launch_bounds__(128, 8) void roi_align_avg_kernel(
    const float* __restrict__ rois,
    const float* __restrict__ scale_p,
    float* __restrict__ out)
{
    __shared__ __align__(16) float s_out[HALF_C * OUTP * OUTP];   // 25088 B

    const int n    = blockIdx.x;
    const int half = blockIdx.y;
    const int tid  = threadIdx.x;                   // 0..127
    const int c    = half * HALF_C + tid;           // channel

    const float scale = scale_p[0];
    const float* r = rois + (size_t)n * 5;
    const int   b  = (int)r[0];
    const float x1 = r[1] * scale;
    const float y1 = r[2] * scale;
    const float x2 = r[3] * scale;
    const float y2 = r[4] * scale;

    const float bw = fmaxf(x2 - x1, 0.0f) / (float)(GRIDP - 1);
    const float bh = fmaxf(y2 - y1, 0.0f) / (float)(GRIDP - 1);

    int   x0i[GRIDP];
    float lx[GRIDP];
    float vxm[GRIDP];
    #pragma unroll
    for (int g = 0; g < GRIDP; ++g) {
        float xs = x1 + (float)g * bw;
        vxm[g]   = (xs >= 0.0f && xs < (float)Wf) ? 1.0f : 0.0f;
        float xf = fminf(fmaxf(floorf(xs), 0.0f), (float)(Wf - 2));
        x0i[g]   = (int)xf;
        lx[g]    = xs - xf;
    }

    const __half* fb = g_featT + (size_t)b * HWf * C_CH + c;

    float prev[GRIDP];
    #pragma unroll
    for (int gy = 0; gy < GRIDP; ++gy) {
        float ys  = y1 + (float)gy * bh;
        float vym = (ys >= 0.0f && ys < (float)Hf) ? 1.0f : 0.0f;
        float yf  = fminf(fmaxf(floorf(ys), 0.0f), (float)(Hf - 2));
        int   y0  = (int)yf;
        float ly  = ys - yf;

        const __half* row0 = fb + (size_t)y0 * (Wf * C_CH);

        float cur[GRIDP];
        // Two half-row batches of 16 taps each: good MLP, bounded live range.
        #pragma unroll
        for (int hb = 0; hb < 2; ++hb) {
            __half t00[4], t01[4], t10[4], t11[4];
            #pragma unroll
            for (int k = 0; k < 4; ++k) {
                int gx = hb * 4 + k;
                const __half* p = row0 + x0i[gx] * C_CH;
                t00[k] = p[0];
                t01[k] = p[C_CH];
                t10[k] = p[Wf * C_CH];
                t11[k] = p[Wf * C_CH + C_CH];
            }
            #pragma unroll
            for (int k = 0; k < 4; ++k) {
                int gx = hb * 4 + k;
                float v00 = __half2float(t00[k]);
                float v01 = __half2float(t01[k]);
                float v10 = __half2float(t10[k]);
                float v11 = __half2float(t11[k]);
                float m  = vym * vxm[gx];
                float tx = v00 + lx[gx] * (v01 - v00);
                float bx = v10 + lx[gx] * (v11 - v10);
                cur[gx]  = (tx + ly * (bx - tx)) * m;
            }
        }

        if (gy > 0) {
            #pragma unroll
            for (int ox = 0; ox < OUTP; ++ox)
                s_out[tid * (OUTP * OUTP) + (gy - 1) * OUTP + ox] =
                    0.25f * (prev[ox] + prev[ox + 1] + cur[ox] + cur[ox + 1]);
        }
        #pragma unroll
        for (int i = 0; i < GRIDP; ++i) prev[i] = cur[i];
    }

    __syncthreads();

    // Dense coalesced write: 128ch * 49 = 6272 floats = 1568 float4
    float4*       o4 = (float4*)(out + (size_t)n * (C_CH * OUTP * OUTP)
                                      + (size_t)half * (HALF_C * OUTP * OUTP));
    const float4* s4 = (const float4*)s_out;
    const int n4 = (HALF_C * OUTP * OUTP) / 4;     // 1568
    for (int i = tid; i < n4; i += 128)
        o4[i] = s4[i];
}

extern "C" void kernel_launch(void* const* d_in, const int* in_sizes, int n_in,
                              void* d_out, int out_size) {
    const float* feat  = (const float*)d_in[0];
    const float* rois  = (const float*)d_in[1];
    const float* scale = (const float*)d_in[2];
    float*       out   = (float*)d_out;

    const int B = in_sizes[0] / (C_CH * HWf);   // 2
    const int N = in_sizes[1] / 5;              // 2048

    dim3 tb(32, 8);
    dim3 tg((HWf + 31) / 32, C_CH / 64, B);
    nchw_to_nhwc_kernel<<<tg, tb>>>(feat);

    dim3 rg(N, C_CH / HALF_C);
    roi_align_avg_kernel<<<rg, 128>>>(rois, scale, out);
}

// round 8
// speedup vs baseline: 1.2432x; 1.2432x over previous
#include <cuda_runtime.h>
#include <cuda_fp16.h>

#define C_CH   256
#define Hf     100
#define Wf     100
#define HWf    (Hf * Wf)
#define GRIDP  8
#define OUTP   7
#define HALF_C 128

// Channel-PERMUTED NHWC scratch in fp16: [B][H][W][C'], B<=2.
// Within each 128-channel half, scratch pair (2t, 2t+1) = orig channels
// (t, t+64). This makes the roi kernel's smem staging conflict-free while
// keeping the staged buffer in exact output channel order.
__device__ __align__(16) __half g_featT[2 * HWf * C_CH];

// ---------------------------------------------------------------------------
// Kernel 1: NCHW fp32 -> permuted-NHWC fp16 transpose.
// Tile 128 channels x 32 hw, block (32,8)=256 threads.
// Load: lanes over hw (128B/warp). Store: half2(orig t, orig t+64) with lanes
// over pairs -> 128B contiguous per warp request.
// ---------------------------------------------------------------------------
__global__ void nchw_to_nhwc_kernel(const float* __restrict__ in) {
    __shared__ float tile[128][33];
    const int b   = blockIdx.z;
    const int hw0 = blockIdx.x * 32;
    const int c0  = blockIdx.y * 128;        // 0 or 128
    const int tx  = threadIdx.x;             // 0..31
    const int ty  = threadIdx.y;             // 0..7

    const float* inb = in + (size_t)b * C_CH * HWf;
    const int hw_l = hw0 + tx;
    if (hw_l < HWf) {
        #pragma unroll
        for (int j = 0; j < 16; ++j) {
            int cl = ty + j * 8;              // 0..127
            tile[cl][tx] = inb[(size_t)(c0 + cl) * HWf + hw_l];
        }
    }
    __syncthreads();

    __half* outb = g_featT + (size_t)b * HWf * C_CH;
    #pragma unroll
    for (int j = 0; j < 4; ++j) {
        int hwl = ty + j * 8;                 // 0..31
        int hw  = hw0 + hwl;
        if (hw < HWf) {
            // pair p = tx  : scratch c0+2tx    <- (orig c0+tx,    orig c0+tx+64)
            __half2 h0 = __floats2half2_rn(tile[tx][hwl], tile[tx + 64][hwl]);
            *(__half2*)(outb + (size_t)hw * C_CH + c0 + 2 * tx) = h0;
            // pair p = tx+32: scratch c0+64+2tx <- (orig c0+tx+32, orig c0+tx+96)
            __half2 h1 = __floats2half2_rn(tile[tx + 32][hwl], tile[tx + 96][hwl]);
            *(__half2*)(outb + (size_t)hw * C_CH + c0 + 64 + 2 * tx) = h1;
        }
    }
}

// ---------------------------------------------------------------------------
// Kernel 2: RoIAlign (8x8 grid) + 2x2/s1 avg pool.
// block = (roi n, channel-half of 128), 64 threads, thread = permuted channel
// pair = orig channels (t, t+64). Batched half2 taps, gy fully unrolled.
// Pooling staged to smem rows t and t+64 (lane stride 49 floats = odd =>
// conflict-free STS). Buffer is the block's exact contiguous output chunk,
// flushed by ONE 1D bulk TMA store (no LDS/STG wavefronts at all).
// ---------------------------------------------------------------------------
__global__ __launch_bounds__(64, 9) void roi_align_avg_kernel(
    const float* __restrict__ rois,
    const float* __restrict__ scale_p,
    float* __restrict__ out)
{
    __shared__ __align__(16) float s_out[HALF_C * OUTP * OUTP];   // 25088 B

    const int n    = blockIdx.x;
    const int half = blockIdx.y;
    const int tid  = threadIdx.x;                   // 0..63
    const int c    = half * HALF_C + tid * 2;       // permuted pair base

    const float scale = scale_p[0];
    const float* r = rois + (size_t)n * 5;
    const int   b  = (int)r[0];
    const float x1 = r[1] * scale;
    const float y1 = r[2] * scale;
    const float x2 = r[3] * scale;
    const float y2 = r[4] * scale;

    const float bw = fmaxf(x2 - x1, 0.0f) / (float)(GRIDP - 1);
    const float bh = fmaxf(y2 - y1, 0.0f) / (float)(GRIDP - 1);

    int   x0i[GRIDP];
    float lx[GRIDP];
    float vxm[GRIDP];
    #pragma unroll
    for (int g = 0; g < GRIDP; ++g) {
        float xs = x1 + (float)g * bw;
        vxm[g]   = (xs >= 0.0f && xs < (float)Wf) ? 1.0f : 0.0f;
        float xf = fminf(fmaxf(floorf(xs), 0.0f), (float)(Wf - 2));
        x0i[g]   = (int)xf;
        lx[g]    = xs - xf;
    }

    const __half* fb = g_featT + (size_t)b * HWf * C_CH + c;

    float2 prev[GRIDP];
    #pragma unroll
    for (int gy = 0; gy < GRIDP; ++gy) {
        float ys  = y1 + (float)gy * bh;
        float vym = (ys >= 0.0f && ys < (float)Hf) ? 1.0f : 0.0f;
        float yf  = fminf(fmaxf(floorf(ys), 0.0f), (float)(Hf - 2));
        int   y0  = (int)yf;
        float ly  = ys - yf;

        const __half* row0 = fb + (size_t)y0 * (Wf * C_CH);

        // Batch all 32 tap loads of this sample row (max MLP).
        __half2 h00[GRIDP], h01[GRIDP], h10[GRIDP], h11[GRIDP];
        #pragma unroll
        for (int gx = 0; gx < GRIDP; ++gx) {
            const __half* p = row0 + x0i[gx] * C_CH;
            h00[gx] = *(const __half2*)(p);
            h01[gx] = *(const __half2*)(p + C_CH);
            h10[gx] = *(const __half2*)(p + Wf * C_CH);
            h11[gx] = *(const __half2*)(p + Wf * C_CH + C_CH);
        }

        float2 cur[GRIDP];
        #pragma unroll
        for (int gx = 0; gx < GRIDP; ++gx) {
            float2 v00 = __half22float2(h00[gx]);
            float2 v01 = __half22float2(h01[gx]);
            float2 v10 = __half22float2(h10[gx]);
            float2 v11 = __half22float2(h11[gx]);
            float m = vym * vxm[gx];
            float tx, bx;
            tx = v00.x + lx[gx] * (v01.x - v00.x);
            bx = v10.x + lx[gx] * (v11.x - v10.x);
            cur[gx].x = (tx + ly * (bx - tx)) * m;
            tx = v00.y + lx[gx] * (v01.y - v00.y);
            bx = v10.y + lx[gx] * (v11.y - v10.y);
            cur[gx].y = (tx + ly * (bx - tx)) * m;
        }

        if (gy > 0) {
            #pragma unroll
            for (int ox = 0; ox < OUTP; ++ox) {
                float sx = 0.25f * (prev[ox].x + prev[ox + 1].x + cur[ox].x + cur[ox + 1].x);
                float sy = 0.25f * (prev[ox].y + prev[ox + 1].y + cur[ox].y + cur[ox + 1].y);
                int k = (gy - 1) * OUTP + ox;
                s_out[tid * (OUTP * OUTP) + k]        = sx;   // orig ch tid
                s_out[(tid + 64) * (OUTP * OUTP) + k] = sy;   // orig ch tid+64
            }
        }
        #pragma unroll
        for (int i = 0; i < GRIDP; ++i) prev[i] = cur[i];
    }

    __syncthreads();

    // One-shot bulk TMA store: smem buffer == contiguous output chunk.
    if (tid == 0) {
        float* gdst = out + (size_t)n * (C_CH * OUTP * OUTP)
                          + (size_t)half * (HALF_C * OUTP * OUTP);
        unsigned sptr = (unsigned)__cvta_generic_to_shared(s_out);
        asm volatile("fence.proxy.async.shared::cta;" ::: "memory");
        asm volatile(
            "cp.async.bulk.global.shared::cta.bulk_group [%0], [%1], %2;"
            :: "l"(gdst), "r"(sptr), "r"((unsigned)(HALF_C * OUTP * OUTP * 4))
            : "memory");
        asm volatile("cp.async.bulk.commit_group;" ::: "memory");
        asm volatile("cp.async.bulk.wait_group 0;" ::: "memory");
    }
}

extern "C" void kernel_launch(void* const* d_in, const int* in_sizes, int n_in,
                              void* d_out, int out_size) {
    const float* feat  = (const float*)d_in[0];
    const float* rois  = (const float*)d_in[1];
    const float* scale = (const float*)d_in[2];
    float*       out   = (float*)d_out;

    const int B = in_sizes[0] / (C_CH * HWf);   // 2
    const int N = in_sizes[1] / 5;              // 2048

    dim3 tb(32, 8);
    dim3 tg((HWf + 31) / 32, C_CH / 128, B);
    nchw_to_nhwc_kernel<<<tg, tb>>>(feat);

    dim3 rg(N, C_CH / HALF_C);
    roi_align_avg_kernel<<<rg, 64>>>(rois, scale, out);
}

// round 9
// speedup vs baseline: 1.3079x; 1.0520x over previous
#include <cuda_runtime.h>
#include <cuda_fp16.h>

#define C_CH   256
#define Hf     100
#define Wf     100
#define HWf    (Hf * Wf)
#define GRIDP  8
#define OUTP   7
#define HALF_C 128

// Channel-PERMUTED NHWC scratch in fp16: [B][H][W][C'], B<=2.
// Within each 128-channel half, scratch pair (2t, 2t+1) = orig channels
// (t, t+64): makes roi-kernel smem staging conflict-free while keeping the
// staged buffer in exact output channel order.
__device__ __align__(16) __half g_featT[2 * HWf * C_CH];

// ---------------------------------------------------------------------------
// Kernel 1: NCHW fp32 -> permuted-NHWC fp16 transpose.
// ---------------------------------------------------------------------------
__global__ void nchw_to_nhwc_kernel(const float* __restrict__ in) {
    __shared__ float tile[128][33];
    const int b   = blockIdx.z;
    const int hw0 = blockIdx.x * 32;
    const int c0  = blockIdx.y * 128;        // 0 or 128
    const int tx  = threadIdx.x;             // 0..31
    const int ty  = threadIdx.y;             // 0..7

    const float* inb = in + (size_t)b * C_CH * HWf;
    const int hw_l = hw0 + tx;
    if (hw_l < HWf) {
        #pragma unroll
        for (int j = 0; j < 16; ++j) {
            int cl = ty + j * 8;              // 0..127
            tile[cl][tx] = inb[(size_t)(c0 + cl) * HWf + hw_l];
        }
    }
    __syncthreads();

    __half* outb = g_featT + (size_t)b * HWf * C_CH;
    #pragma unroll
    for (int j = 0; j < 4; ++j) {
        int hwl = ty + j * 8;                 // 0..31
        int hw  = hw0 + hwl;
        if (hw < HWf) {
            __half2 h0 = __floats2half2_rn(tile[tx][hwl], tile[tx + 64][hwl]);
            *(__half2*)(outb + (size_t)hw * C_CH + c0 + 2 * tx) = h0;
            __half2 h1 = __floats2half2_rn(tile[tx + 32][hwl], tile[tx + 96][hwl]);
            *(__half2*)(outb + (size_t)hw * C_CH + c0 + 64 + 2 * tx) = h1;
        }
    }
}

// ---------------------------------------------------------------------------
// Kernel 2: RoIAlign (8x8 grid) + 2x2/s1 avg pool.
// block = (roi n, channel-half of 128), 64 threads, thread = permuted channel
// pair = orig channels (t, t+64). Batched half2 taps; X-LERP IN PACKED FP16
// (HSUB2/HFMA2) so only top/bot are converted to fp32 (halves F2F count and
// removes the fp32 x-lerp FFMAs). y-lerp, masking and pooling stay fp32.
// Pooling staged conflict-free in smem; one bulk TMA store flushes the
// block's contiguous output chunk.
// ---------------------------------------------------------------------------
__global__ __launch_bounds__(64, 9) void roi_align_avg_kernel(
    const float* __restrict__ rois,
    const float* __restrict__ scale_p,
    float* __restrict__ out)
{
    __shared__ __align__(16) float s_out[HALF_C * OUTP * OUTP];   // 25088 B

    const int n    = blockIdx.x;
    const int half = blockIdx.y;
    const int tid  = threadIdx.x;                   // 0..63
    const int c    = half * HALF_C + tid * 2;       // permuted pair base

    const float scale = scale_p[0];
    const float* r = rois + (size_t)n * 5;
    const int   b  = (int)r[0];
    const float x1 = r[1] * scale;
    const float y1 = r[2] * scale;
    const float x2 = r[3] * scale;
    const float y2 = r[4] * scale;

    const float bw = fmaxf(x2 - x1, 0.0f) / (float)(GRIDP - 1);
    const float bh = fmaxf(y2 - y1, 0.0f) / (float)(GRIDP - 1);

    int     x0i[GRIDP];
    __half2 lxh[GRIDP];
    float   vxm[GRIDP];
    #pragma unroll
    for (int g = 0; g < GRIDP; ++g) {
        float xs = x1 + (float)g * bw;
        vxm[g]   = (xs >= 0.0f && xs < (float)Wf) ? 1.0f : 0.0f;
        float xf = fminf(fmaxf(floorf(xs), 0.0f), (float)(Wf - 2));
        x0i[g]   = (int)xf;
        lxh[g]   = __float2half2_rn(xs - xf);
    }

    const __half* fb = g_featT + (size_t)b * HWf * C_CH + c;

    float2 prev[GRIDP];
    #pragma unroll
    for (int gy = 0; gy < GRIDP; ++gy) {
        float ys  = y1 + (float)gy * bh;
        float vym = (ys >= 0.0f && ys < (float)Hf) ? 1.0f : 0.0f;
        float yf  = fminf(fmaxf(floorf(ys), 0.0f), (float)(Hf - 2));
        int   y0  = (int)yf;
        float ly  = ys - yf;

        const __half* row0 = fb + (size_t)y0 * (Wf * C_CH);

        // Batch all 32 tap loads of this sample row (max MLP).
        __half2 h00[GRIDP], h01[GRIDP], h10[GRIDP], h11[GRIDP];
        #pragma unroll
        for (int gx = 0; gx < GRIDP; ++gx) {
            const __half* p = row0 + x0i[gx] * C_CH;
            h00[gx] = *(const __half2*)(p);
            h01[gx] = *(const __half2*)(p + C_CH);
            h10[gx] = *(const __half2*)(p + Wf * C_CH);
            h11[gx] = *(const __half2*)(p + Wf * C_CH + C_CH);
        }

        float2 cur[GRIDP];
        #pragma unroll
        for (int gx = 0; gx < GRIDP; ++gx) {
            // x-lerp in packed fp16
            __half2 toph = __hfma2(lxh[gx], __hsub2(h01[gx], h00[gx]), h00[gx]);
            __half2 both = __hfma2(lxh[gx], __hsub2(h11[gx], h10[gx]), h10[gx]);
            float2 top = __half22float2(toph);
            float2 bot = __half22float2(both);
            // y-lerp + mask in fp32
            float m = vym * vxm[gx];
            cur[gx].x = (top.x + ly * (bot.x - top.x)) * m;
            cur[gx].y = (top.y + ly * (bot.y - top.y)) * m;
        }

        if (gy > 0) {
            #pragma unroll
            for (int ox = 0; ox < OUTP; ++ox) {
                float sx = 0.25f * (prev[ox].x + prev[ox + 1].x + cur[ox].x + cur[ox + 1].x);
                float sy = 0.25f * (prev[ox].y + prev[ox + 1].y + cur[ox].y + cur[ox + 1].y);
                int k = (gy - 1) * OUTP + ox;
                s_out[tid * (OUTP * OUTP) + k]        = sx;   // orig ch tid
                s_out[(tid + 64) * (OUTP * OUTP) + k] = sy;   // orig ch tid+64
            }
        }
        #pragma unroll
        for (int i = 0; i < GRIDP; ++i) prev[i] = cur[i];
    }

    __syncthreads();

    // One-shot bulk TMA store: smem buffer == contiguous output chunk.
    if (tid == 0) {
        float* gdst = out + (size_t)n * (C_CH * OUTP * OUTP)
                          + (size_t)half * (HALF_C * OUTP * OUTP);
        unsigned sptr = (unsigned)__cvta_generic_to_shared(s_out);
        asm volatile("fence.proxy.async.shared::cta;" ::: "memory");
        asm volatile(
            "cp.async.bulk.global.shared::cta.bulk_group [%0], [%1], %2;"
            :: "l"(gdst), "r"(sptr), "r"((unsigned)(HALF_C * OUTP * OUTP * 4))
            : "memory");
        asm volatile("cp.async.bulk.commit_group;" ::: "memory");
        asm volatile("cp.async.bulk.wait_group 0;" ::: "memory");
    }
}

extern "C" void kernel_launch(void* const* d_in, const int* in_sizes, int n_in,
                              void* d_out, int out_size) {
    const float* feat  = (const float*)d_in[0];
    const float* rois  = (const float*)d_in[1];
    const float* scale = (const float*)d_in[2];
    float*       out   = (float*)d_out;

    const int B = in_sizes[0] / (C_CH * HWf);   // 2
    const int N = in_sizes[1] / 5;              // 2048

    dim3 tb(32, 8);
    dim3 tg((HWf + 31) / 32, C_CH / 128, B);
    nchw_to_nhwc_kernel<<<tg, tb>>>(feat);

    dim3 rg(N, C_CH / HALF_C);
    roi_align_avg_kernel<<<rg, 64>>>(rois, scale, out);
}

// round 10
// speedup vs baseline: 1.3690x; 1.0468x over previous
#include <cuda_runtime.h>
#include <cuda_fp16.h>

#define C_CH   256
#define Hf     100
#define Wf     100
#define HWf    (Hf * Wf)
#define GRIDP  8
#define OUTP   7
#define HALF_C 128

// Channel-PERMUTED NHWC scratch in fp16: [B][H][W][C'], B<=2.
// Within each 128-channel half, scratch pair (2t, 2t+1) = orig channels
// (t, t+64): conflict-free smem staging + output-ordered staging buffer.
__device__ __align__(16) __half g_featT[2 * HWf * C_CH];

// ---------------------------------------------------------------------------
// Kernel 1: NCHW fp32 -> permuted-NHWC fp16 transpose.
// ---------------------------------------------------------------------------
__global__ void nchw_to_nhwc_kernel(const float* __restrict__ in) {
    __shared__ float tile[128][33];
    const int b   = blockIdx.z;
    const int hw0 = blockIdx.x * 32;
    const int c0  = blockIdx.y * 128;        // 0 or 128
    const int tx  = threadIdx.x;             // 0..31
    const int ty  = threadIdx.y;             // 0..7

    const float* inb = in + (size_t)b * C_CH * HWf;
    const int hw_l = hw0 + tx;
    if (hw_l < HWf) {
        #pragma unroll
        for (int j = 0; j < 16; ++j) {
            int cl = ty + j * 8;              // 0..127
            tile[cl][tx] = inb[(size_t)(c0 + cl) * HWf + hw_l];
        }
    }
    __syncthreads();

    __half* outb = g_featT + (size_t)b * HWf * C_CH;
    #pragma unroll
    for (int j = 0; j < 4; ++j) {
        int hwl = ty + j * 8;                 // 0..31
        int hw  = hw0 + hwl;
        if (hw < HWf) {
            __half2 h0 = __floats2half2_rn(tile[tx][hwl], tile[tx + 64][hwl]);
            *(__half2*)(outb + (size_t)hw * C_CH + c0 + 2 * tx) = h0;
            __half2 h1 = __floats2half2_rn(tile[tx + 32][hwl], tile[tx + 96][hwl]);
            *(__half2*)(outb + (size_t)hw * C_CH + c0 + 64 + 2 * tx) = h1;
        }
    }
}

// ---------------------------------------------------------------------------
// Kernel 2: RoIAlign (8x8 grid) + 2x2/s1 avg pool.
// block = (roi n, channel-half of 128), 64 threads, thread = permuted channel
// pair = orig channels (t, t+64). Batched half2 taps. FULL fp16 sample path:
// x-lerp, y-lerp, validity mask all HFMA2/HMUL2; row-pair sums in HADD2.
// Only the 7 rowsums/row are converted to fp32; final 2-row combine (and the
// staged output) stay fp32. Conflict-free smem staging; one bulk TMA store
// flushes the block's contiguous output chunk.
// ---------------------------------------------------------------------------
__global__ __launch_bounds__(64, 9) void roi_align_avg_kernel(
    const float* __restrict__ rois,
    const float* __restrict__ scale_p,
    float* __restrict__ out)
{
    __shared__ __align__(16) float s_out[HALF_C * OUTP * OUTP];   // 25088 B

    const int n    = blockIdx.x;
    const int half = blockIdx.y;
    const int tid  = threadIdx.x;                   // 0..63
    const int c    = half * HALF_C + tid * 2;       // permuted pair base

    const float scale = scale_p[0];
    const float* r = rois + (size_t)n * 5;
    const int   b  = (int)r[0];
    const float x1 = r[1] * scale;
    const float y1 = r[2] * scale;
    const float x2 = r[3] * scale;
    const float y2 = r[4] * scale;

    const float bw = fmaxf(x2 - x1, 0.0f) / (float)(GRIDP - 1);
    const float bh = fmaxf(y2 - y1, 0.0f) / (float)(GRIDP - 1);

    int     x0i[GRIDP];
    __half2 lxh[GRIDP];
    __half2 vxh[GRIDP];
    #pragma unroll
    for (int g = 0; g < GRIDP; ++g) {
        float xs = x1 + (float)g * bw;
        vxh[g]   = __float2half2_rn((xs >= 0.0f && xs < (float)Wf) ? 1.0f : 0.0f);
        float xf = fminf(fmaxf(floorf(xs), 0.0f), (float)(Wf - 2));
        x0i[g]   = (int)xf;
        lxh[g]   = __float2half2_rn(xs - xf);
    }

    const __half* fb = g_featT + (size_t)b * HWf * C_CH + c;

    float2 prevs[OUTP];   // previous row's pair-sums (fp32)
    #pragma unroll
    for (int gy = 0; gy < GRIDP; ++gy) {
        float ys  = y1 + (float)gy * bh;
        float vym = (ys >= 0.0f && ys < (float)Hf) ? 1.0f : 0.0f;
        float yf  = fminf(fmaxf(floorf(ys), 0.0f), (float)(Hf - 2));
        int   y0  = (int)yf;
        __half2 lyh  = __float2half2_rn(ys - yf);
        __half2 vymh = __float2half2_rn(vym);

        const __half* row0 = fb + (size_t)y0 * (Wf * C_CH);

        // Batch all 32 tap loads of this sample row (max MLP).
        __half2 h00[GRIDP], h01[GRIDP], h10[GRIDP], h11[GRIDP];
        #pragma unroll
        for (int gx = 0; gx < GRIDP; ++gx) {
            const __half* p = row0 + x0i[gx] * C_CH;
            h00[gx] = *(const __half2*)(p);
            h01[gx] = *(const __half2*)(p + C_CH);
            h10[gx] = *(const __half2*)(p + Wf * C_CH);
            h11[gx] = *(const __half2*)(p + Wf * C_CH + C_CH);
        }

        // Sample entirely in packed fp16.
        __half2 cur[GRIDP];
        #pragma unroll
        for (int gx = 0; gx < GRIDP; ++gx) {
            __half2 toph = __hfma2(lxh[gx], __hsub2(h01[gx], h00[gx]), h00[gx]);
            __half2 both = __hfma2(lxh[gx], __hsub2(h11[gx], h10[gx]), h10[gx]);
            __half2 yl   = __hfma2(lyh, __hsub2(both, toph), toph);
            cur[gx]      = __hmul2(yl, __hmul2(vxh[gx], vymh));
        }

        // Separable pooling: adjacent-pair sums in fp16, convert once.
        float2 curs[OUTP];
        #pragma unroll
        for (int ox = 0; ox < OUTP; ++ox)
            curs[ox] = __half22float2(__hadd2(cur[ox], cur[ox + 1]));

        if (gy > 0) {
            #pragma unroll
            for (int ox = 0; ox < OUTP; ++ox) {
                int k = (gy - 1) * OUTP + ox;
                s_out[tid * (OUTP * OUTP) + k] =
                    0.25f * (prevs[ox].x + curs[ox].x);            // orig ch tid
                s_out[(tid + 64) * (OUTP * OUTP) + k] =
                    0.25f * (prevs[ox].y + curs[ox].y);            // orig ch tid+64
            }
        }
        #pragma unroll
        for (int i = 0; i < OUTP; ++i) prevs[i] = curs[i];
    }

    __syncthreads();

    // One-shot bulk TMA store: smem buffer == contiguous output chunk.
    if (tid == 0) {
        float* gdst = out + (size_t)n * (C_CH * OUTP * OUTP)
                          + (size_t)half * (HALF_C * OUTP * OUTP);
        unsigned sptr = (unsigned)__cvta_generic_to_shared(s_out);
        asm volatile("fence.proxy.async.shared::cta;" ::: "memory");
        asm volatile(
            "cp.async.bulk.global.shared::cta.bulk_group [%0], [%1], %2;"
            :: "l"(gdst), "r"(sptr), "r"((unsigned)(HALF_C * OUTP * OUTP * 4))
            : "memory");
        asm volatile("cp.async.bulk.commit_group;" ::: "memory");
        asm volatile("cp.async.bulk.wait_group 0;" ::: "memory");
    }
}

extern "C" void kernel_launch(void* const* d_in, const int* in_sizes, int n_in,
                              void* d_out, int out_size) {
    const float* feat  = (const float*)d_in[0];
    const float* rois  = (const float*)d_in[1];
    const float* scale = (const float*)d_in[2];
    float*       out   = (float*)d_out;

    const int B = in_sizes[0] / (C_CH * HWf);   // 2
    const int N = in_sizes[1] / 5;              // 2048

    dim3 tb(32, 8);
    dim3 tg((HWf + 31) / 32, C_CH / 128, B);
    nchw_to_nhwc_kernel<<<tg, tb>>>(feat);

    dim3 rg(N, C_CH / HALF_C);
    roi_align_avg_kernel<<<rg, 64>>>(rois, scale, out);
}